// round 16
// baseline (speedup 1.0000x reference)
#include <cuda_runtime.h>
#include <cuda_bf16.h>
#include <cuda_fp16.h>
#include <cstdint>

#define N_NODES 50000
#define N_EDGES 640000
#define HD      128
#define T_TGT   100
#define NBLD    148                         // build kernel blocks (1 per SM)

// ---------------- scratch (static device globals) ---------------------------
__device__ float g_deg   [N_NODES];
__device__ int   g_cnt   [N_NODES];
__device__ int   g_rowptr[N_NODES + 1];
__device__ int   g_pos   [N_EDGES];
__device__ int2  g_ecsr  [N_EDGES];
__device__ int   g_bsum  [NBLD];
__device__ unsigned g_arrive  = 0;          // monotonic grid-barrier counters
__device__ unsigned g_release = 0;          // (never reset -> replay-safe)
__device__ __align__(16) __half g_xwA[N_NODES * HD];
__device__ __align__(16) __half g_xwB[N_NODES * HD];
// interleaved bf16 planes: per 4-col group one uint4 {hi01, hi23, lo01, lo23}
__device__ __align__(16) uint4 g_apk [N_NODES * 32];
__device__ __align__(16) uint4 g_w2pk[HD * 32];
__device__ __align__(16) uint4 g_w3pk[HD * 32];

// ---------------- bf16 split helper ------------------------------------------
__device__ __forceinline__ void split2(float a, float b, uint32_t& hi, uint32_t& lo) {
    __nv_bfloat16 ha = __float2bfloat16_rn(a);
    __nv_bfloat16 hb = __float2bfloat16_rn(b);
    float ra = a - __bfloat162float(ha);
    float rb = b - __bfloat162float(hb);
    __nv_bfloat162 H; H.x = ha; H.y = hb;
    __nv_bfloat162 L; L.x = __float2bfloat16_rn(ra); L.y = __float2bfloat16_rn(rb);
    hi = *(uint32_t*)&H;
    lo = *(uint32_t*)&L;
}

// ---------------- software grid barrier (all NBLD blocks resident) -----------
__device__ __forceinline__ void gsync() {
    __threadfence();
    __syncthreads();
    if (threadIdx.x == 0) {
        unsigned old = atomicAdd(&g_arrive, 1u);
        unsigned gen = old / NBLD;
        if ((old % NBLD) == NBLD - 1) {
            atomicAdd(&g_release, 1u);
        } else {
            while (atomicAdd(&g_release, 0u) <= gen) __nanosleep(64);
        }
        __threadfence();
    }
    __syncthreads();
}

// ---------------- fused CSR build: init+splitW / deg_count / scan / bucket ---
__global__ __launch_bounds__(256) void k_build(const float* __restrict__ W2,
                                               const float* __restrict__ W3,
                                               const int* __restrict__ src,
                                               const int* __restrict__ dst,
                                               const float* __restrict__ ew) {
    const int tid = threadIdx.x;
    const int t   = blockIdx.x * 256 + tid;
    const int NT  = NBLD * 256;
    __shared__ int sh[256];

    // P0: init counters + pre-split W2/W3 (interleaved planes)
    for (int i = t; i < N_NODES; i += NT) { g_deg[i] = 1.0f; g_cnt[i] = 0; }
    for (int i = t; i < HD * HD / 4; i += NT) {
        float4 v = ((const float4*)W2)[i];
        uint32_t h0, l0, h1, l1;
        split2(v.x, v.y, h0, l0);
        split2(v.z, v.w, h1, l1);
        g_w2pk[i] = make_uint4(h0, h1, l0, l1);
        v = ((const float4*)W3)[i];
        split2(v.x, v.y, h0, l0);
        split2(v.z, v.w, h1, l1);
        g_w3pk[i] = make_uint4(h0, h1, l0, l1);
    }
    gsync();

    // P1: degree + slot assignment
    for (int e = t; e < N_EDGES; e += NT) {
        int d = dst[e];
        g_pos[e] = atomicAdd(&g_cnt[d], 1);
        atomicAdd(&g_deg[d], ew[e]);
    }
    gsync();

    // P2: chunked exclusive scan (C nodes per thread) + dinv
    const int C = (N_NODES + NT - 1) / NT;   // 2
    int lo = t * C;
    int hi = lo + C; if (hi > N_NODES) hi = N_NODES;
    int c0 = 0, c1 = 0, s = 0;
    if (lo < N_NODES) { c0 = g_cnt[lo]; s += c0; }
    if (lo + 1 < hi)  { c1 = g_cnt[lo + 1]; s += c1; }
    sh[tid] = s;
    __syncthreads();
    for (int off = 1; off < 256; off <<= 1) {
        int x = (tid >= off) ? sh[tid - off] : 0;
        __syncthreads();
        sh[tid] += x;
        __syncthreads();
    }
    int excl = sh[tid] - s;
    if (tid == 0) g_bsum[blockIdx.x] = sh[255];
    gsync();                                  // bsum visible; also fences sh reads
    sh[tid] = (tid < blockIdx.x) ? g_bsum[tid] : 0;   // tid<148<=255 covers all blocks
    __syncthreads();
    for (int off = 128; off > 0; off >>= 1) {
        if (tid < off) sh[tid] += sh[tid + off];
        __syncthreads();
    }
    int run = sh[0] + excl;
    if (lo < N_NODES) {
        g_rowptr[lo] = run; run += c0;
        float d0 = g_deg[lo]; g_deg[lo] = rsqrtf(fmaxf(d0, 1e-12f));
    }
    if (lo + 1 < hi) {
        g_rowptr[lo + 1] = run; run += c1;
        float d1 = g_deg[lo + 1]; g_deg[lo + 1] = rsqrtf(fmaxf(d1, 1e-12f));
    }
    if (t == 0) g_rowptr[N_NODES] = N_EDGES;
    gsync();

    // P3: bucket edges into CSR slots with coefficients
    for (int e = t; e < N_EDGES; e += NT) {
        int d  = dst[e];
        int sn = src[e];
        float c = g_deg[sn] * ew[e] * g_deg[d];
        g_ecsr[g_rowptr[d] + g_pos[e]] = make_int2(sn, __float_as_int(c));
    }
}

// ---------------- mma helpers ------------------------------------------------
__device__ __forceinline__ void ldm_x4(uint32_t r[4], uint32_t addr) {
    asm volatile("ldmatrix.sync.aligned.m8n8.x4.shared.b16 {%0,%1,%2,%3}, [%4];"
                 : "=r"(r[0]), "=r"(r[1]), "=r"(r[2]), "=r"(r[3]) : "r"(addr));
}
__device__ __forceinline__ void ldm_x2t(uint32_t r[2], uint32_t addr) {
    asm volatile("ldmatrix.sync.aligned.m8n8.x2.trans.shared.b16 {%0,%1}, [%2];"
                 : "=r"(r[0]), "=r"(r[1]) : "r"(addr));
}
__device__ __forceinline__ void mma_bf16(float c[4], const uint32_t a[4], const uint32_t b[2]) {
    asm volatile("mma.sync.aligned.m16n8k16.row.col.f32.bf16.bf16.f32 "
                 "{%0,%1,%2,%3}, {%4,%5,%6,%7}, {%8,%9}, {%0,%1,%2,%3};"
                 : "+f"(c[0]), "+f"(c[1]), "+f"(c[2]), "+f"(c[3])
                 : "r"(a[0]), "r"(a[1]), "r"(a[2]), "r"(a[3]), "r"(b[0]), "r"(b[1]));
}

// ---------------- layer-1 GEMM: xw(fp16) = x(fp32) @ W (on-the-fly split) ---
__global__ __launch_bounds__(256, 2) void k_gemm1(const float* __restrict__ A,
                                                  const float* __restrict__ W,
                                                  __half* __restrict__ Cxw, int M) {
    __shared__ uint32_t As_hi[64][20], As_lo[64][20];
    __shared__ uint32_t Bs_hi[32][68], Bs_lo[32][68];

    const int tid  = threadIdx.x;
    const int lane = tid & 31;
    const int wid  = tid >> 5;
    const int g    = lane >> 2;
    const int tig  = lane & 3;
    const int wm   = wid >> 2;
    const int wn   = wid & 3;
    const int row0 = blockIdx.x * 64;

    const uint32_t aH = (uint32_t)__cvta_generic_to_shared(&As_hi[0][0]);
    const uint32_t aL = (uint32_t)__cvta_generic_to_shared(&As_lo[0][0]);
    const uint32_t bH = (uint32_t)__cvta_generic_to_shared(&Bs_hi[0][0]);
    const uint32_t bL = (uint32_t)__cvta_generic_to_shared(&Bs_lo[0][0]);

    float acc[2][4][4];
#pragma unroll
    for (int mt = 0; mt < 2; mt++)
#pragma unroll
        for (int nt = 0; nt < 4; nt++)
#pragma unroll
            for (int i = 0; i < 4; i++) acc[mt][nt][i] = 0.0f;

    for (int k0 = 0; k0 < 128; k0 += 32) {
#pragma unroll
        for (int it = 0; it < 2; it++) {
            int idx = tid + it * 256;
            int r   = idx >> 3;
            int c4  = (idx & 7) * 4;
            float4 v = make_float4(0.f, 0.f, 0.f, 0.f);
            int gr = row0 + r;
            if (gr < M) v = *(const float4*)(A + (long)gr * 128 + k0 + c4);
            uint32_t h0, l0, h1, l1;
            split2(v.x, v.y, h0, l0);
            split2(v.z, v.w, h1, l1);
            int cw = c4 >> 1;
            As_hi[r][cw] = h0; As_hi[r][cw + 1] = h1;
            As_lo[r][cw] = l0; As_lo[r][cw + 1] = l1;
        }
#pragma unroll
        for (int it = 0; it < 4; it++) {
            int idx = tid + it * 256;
            int kr  = idx >> 5;
            int c4  = (idx & 31) * 4;
            float4 v = *(const float4*)(W + (long)(k0 + kr) * 128 + c4);
            uint32_t h0, l0, h1, l1;
            split2(v.x, v.y, h0, l0);
            split2(v.z, v.w, h1, l1);
            int cw = c4 >> 1;
            Bs_hi[kr][cw] = h0; Bs_hi[kr][cw + 1] = h1;
            Bs_lo[kr][cw] = l0; Bs_lo[kr][cw + 1] = l1;
        }
        __syncthreads();

#pragma unroll
        for (int kk = 0; kk < 32; kk += 16) {
            uint32_t Ah[2][4], Al[2][4];
#pragma unroll
            for (int mt = 0; mt < 2; mt++) {
                uint32_t off = (uint32_t)(wm * 32 + mt * 16 + (lane & 15)) * 80u
                             + (uint32_t)(kk + ((lane >> 4) << 3)) * 2u;
                ldm_x4(Ah[mt], aH + off);
                ldm_x4(Al[mt], aL + off);
            }
#pragma unroll
            for (int nt = 0; nt < 4; nt++) {
                uint32_t Bh[2], Bl[2];
                uint32_t off = (uint32_t)(kk + (lane & 15)) * 272u
                             + (uint32_t)(wn * 32 + nt * 8) * 2u;
                ldm_x2t(Bh, bH + off);
                ldm_x2t(Bl, bL + off);
#pragma unroll
                for (int mt = 0; mt < 2; mt++) {
                    mma_bf16(acc[mt][nt], Ah[mt], Bh);
                    mma_bf16(acc[mt][nt], Ah[mt], Bl);
                    mma_bf16(acc[mt][nt], Al[mt], Bh);
                }
            }
        }
        __syncthreads();
    }

    __half2* xh2 = (__half2*)Cxw;
#pragma unroll
    for (int mt = 0; mt < 2; mt++) {
        int r0 = row0 + wm * 32 + mt * 16 + g;
        int r1 = r0 + 8;
#pragma unroll
        for (int nt = 0; nt < 4; nt++) {
            int colh = (wn * 32 + nt * 8 + 2 * tig) >> 1;
            if (r0 < M)
                xh2[(long)r0 * 64 + colh] = __floats2half2_rn(acc[mt][nt][0], acc[mt][nt][1]);
            if (r1 < M)
                xh2[(long)r1 * 64 + colh] = __floats2half2_rn(acc[mt][nt][2], acc[mt][nt][3]);
        }
    }
}

// ---------------- pre-split GEMM: xw(fp16) = Apk @ Wpk (interleaved planes) --
__global__ __launch_bounds__(256, 2) void k_gemm_ps(const uint4* __restrict__ apk,
                                                    const uint4* __restrict__ wpk,
                                                    __half* __restrict__ Cxw, int M) {
    __shared__ uint32_t As_hi[64][20], As_lo[64][20];
    __shared__ uint32_t Bs_hi[32][68], Bs_lo[32][68];

    const int tid  = threadIdx.x;
    const int lane = tid & 31;
    const int wid  = tid >> 5;
    const int g    = lane >> 2;
    const int tig  = lane & 3;
    const int wm   = wid >> 2;
    const int wn   = wid & 3;
    const int row0 = blockIdx.x * 64;

    const uint32_t aH = (uint32_t)__cvta_generic_to_shared(&As_hi[0][0]);
    const uint32_t aL = (uint32_t)__cvta_generic_to_shared(&As_lo[0][0]);
    const uint32_t bH = (uint32_t)__cvta_generic_to_shared(&Bs_hi[0][0]);
    const uint32_t bL = (uint32_t)__cvta_generic_to_shared(&Bs_lo[0][0]);

    float acc[2][4][4];
#pragma unroll
    for (int mt = 0; mt < 2; mt++)
#pragma unroll
        for (int nt = 0; nt < 4; nt++)
#pragma unroll
            for (int i = 0; i < 4; i++) acc[mt][nt][i] = 0.0f;

    for (int k0 = 0; k0 < 128; k0 += 32) {
#pragma unroll
        for (int it = 0; it < 2; it++) {
            int idx = tid + it * 256;
            int r   = idx >> 3;
            int wg  = idx & 7;
            int gr  = row0 + r;
            uint4 u = make_uint4(0u, 0u, 0u, 0u);
            if (gr < M) u = apk[(long)gr * 32 + (k0 >> 2) + wg];
            As_hi[r][wg * 2] = u.x; As_hi[r][wg * 2 + 1] = u.y;
            As_lo[r][wg * 2] = u.z; As_lo[r][wg * 2 + 1] = u.w;
        }
#pragma unroll
        for (int it = 0; it < 4; it++) {
            int idx = tid + it * 256;
            int kr  = idx >> 5;
            int cg  = idx & 31;
            uint4 u = wpk[(long)(k0 + kr) * 32 + cg];
            Bs_hi[kr][cg * 2] = u.x; Bs_hi[kr][cg * 2 + 1] = u.y;
            Bs_lo[kr][cg * 2] = u.z; Bs_lo[kr][cg * 2 + 1] = u.w;
        }
        __syncthreads();

#pragma unroll
        for (int kk = 0; kk < 32; kk += 16) {
            uint32_t Ah[2][4], Al[2][4];
#pragma unroll
            for (int mt = 0; mt < 2; mt++) {
                uint32_t off = (uint32_t)(wm * 32 + mt * 16 + (lane & 15)) * 80u
                             + (uint32_t)(kk + ((lane >> 4) << 3)) * 2u;
                ldm_x4(Ah[mt], aH + off);
                ldm_x4(Al[mt], aL + off);
            }
#pragma unroll
            for (int nt = 0; nt < 4; nt++) {
                uint32_t Bh[2], Bl[2];
                uint32_t off = (uint32_t)(kk + (lane & 15)) * 272u
                             + (uint32_t)(wn * 32 + nt * 8) * 2u;
                ldm_x2t(Bh, bH + off);
                ldm_x2t(Bl, bL + off);
#pragma unroll
                for (int mt = 0; mt < 2; mt++) {
                    mma_bf16(acc[mt][nt], Ah[mt], Bh);
                    mma_bf16(acc[mt][nt], Ah[mt], Bl);
                    mma_bf16(acc[mt][nt], Al[mt], Bh);
                }
            }
        }
        __syncthreads();
    }

    __half2* xh2 = (__half2*)Cxw;
#pragma unroll
    for (int mt = 0; mt < 2; mt++) {
        int r0 = row0 + wm * 32 + mt * 16 + g;
        int r1 = r0 + 8;
#pragma unroll
        for (int nt = 0; nt < 4; nt++) {
            int colh = (wn * 32 + nt * 8 + 2 * tig) >> 1;
            if (r0 < M)
                xh2[(long)r0 * 64 + colh] = __floats2half2_rn(acc[mt][nt][0], acc[mt][nt][1]);
            if (r1 < M)
                xh2[(long)r1 * 64 + colh] = __floats2half2_rn(acc[mt][nt][2], acc[mt][nt][3]);
        }
    }
}

// ---------------- CSR gather + bias + relu -> interleaved bf16 planes --------
__global__ __launch_bounds__(256) void k_gather_ps(const __half* __restrict__ xw,
                                                   const float* __restrict__ bias,
                                                   uint4* __restrict__ apk) {
    int node = (blockIdx.x * blockDim.x + threadIdx.x) >> 5;
    int lane = threadIdx.x & 31;
    if (node >= N_NODES) return;

    int beg = g_rowptr[node];
    int end = g_rowptr[node + 1];
    float di = g_deg[node];
    float s  = di * di;

    const uint2* xv = (const uint2*)xw;

    float4 acc;
    {
        uint2 u = __ldg(&xv[(long)node * 32 + lane]);
        float2 a = __half22float2(*(__half2*)&u.x);
        float2 b = __half22float2(*(__half2*)&u.y);
        acc = make_float4(s * a.x, s * a.y, s * b.x, s * b.y);
    }

    int i = beg;
    for (; i + 8 <= end; i += 8) {
        int2  p[8];
        uint2 u[8];
#pragma unroll
        for (int j = 0; j < 8; j++) p[j] = __ldg(&g_ecsr[i + j]);
#pragma unroll
        for (int j = 0; j < 8; j++) u[j] = __ldg(&xv[(long)p[j].x * 32 + lane]);
#pragma unroll
        for (int j = 0; j < 8; j++) {
            float c = __int_as_float(p[j].y);
            float2 a = __half22float2(*(__half2*)&u[j].x);
            float2 b = __half22float2(*(__half2*)&u[j].y);
            acc.x += c * a.x; acc.y += c * a.y; acc.z += c * b.x; acc.w += c * b.y;
        }
    }
    for (; i + 2 <= end; i += 2) {
        int2 p0 = __ldg(&g_ecsr[i]);
        int2 p1 = __ldg(&g_ecsr[i + 1]);
        uint2 u0 = __ldg(&xv[(long)p0.x * 32 + lane]);
        uint2 u1 = __ldg(&xv[(long)p1.x * 32 + lane]);
        float c0 = __int_as_float(p0.y), c1 = __int_as_float(p1.y);
        float2 a, b;
        a = __half22float2(*(__half2*)&u0.x); b = __half22float2(*(__half2*)&u0.y);
        acc.x += c0 * a.x; acc.y += c0 * a.y; acc.z += c0 * b.x; acc.w += c0 * b.y;
        a = __half22float2(*(__half2*)&u1.x); b = __half22float2(*(__half2*)&u1.y);
        acc.x += c1 * a.x; acc.y += c1 * a.y; acc.z += c1 * b.x; acc.w += c1 * b.y;
    }
    if (i < end) {
        int2 p = __ldg(&g_ecsr[i]);
        float c = __int_as_float(p.y);
        uint2 u = __ldg(&xv[(long)p.x * 32 + lane]);
        float2 a = __half22float2(*(__half2*)&u.x);
        float2 b = __half22float2(*(__half2*)&u.y);
        acc.x += c * a.x; acc.y += c * a.y; acc.z += c * b.x; acc.w += c * b.y;
    }

    float4 bb = *(const float4*)(bias + lane * 4);
    acc.x = fmaxf(acc.x + bb.x, 0.f);
    acc.y = fmaxf(acc.y + bb.y, 0.f);
    acc.z = fmaxf(acc.z + bb.z, 0.f);
    acc.w = fmaxf(acc.w + bb.w, 0.f);

    uint32_t h0, l0, h1, l1;
    split2(acc.x, acc.y, h0, l0);
    split2(acc.z, acc.w, h1, l1);
    apk[(long)node * 32 + lane] = make_uint4(h0, h1, l0, l1);
}

// ---------------- head: per-target CSR gather + MLP --------------------------
__global__ __launch_bounds__(128) void k_head(const __half* __restrict__ xw3,
                                              const float* __restrict__ b3,
                                              const int* __restrict__ ace_idx,
                                              const int* __restrict__ h2_idx,
                                              const float* __restrict__ Wh,
                                              const float* __restrict__ bh,
                                              const float* __restrict__ Wace,
                                              const float* __restrict__ bace,
                                              const float* __restrict__ Wh2,
                                              const float* __restrict__ bh2,
                                              float* __restrict__ out) {
    __shared__ float rs[128];
    __shared__ float red[4];
    int bt    = blockIdx.x;
    int which = bt / T_TGT;
    int t     = bt - which * T_TGT;
    int node  = which ? h2_idx[t] : ace_idx[t];
    int j     = threadIdx.x;

    float di  = g_deg[node];
    float acc = di * di * __half2float(xw3[(long)node * 128 + j]);
    int beg = g_rowptr[node];
    int end = g_rowptr[node + 1];
    for (int i = beg; i < end; i++) {
        int2 p = g_ecsr[i];
        acc += __int_as_float(p.y) * __half2float(xw3[(long)p.x * 128 + j]);
    }
    rs[j] = fmaxf(acc + b3[j], 0.f);
    __syncthreads();

    float a2 = 0.f;
#pragma unroll 8
    for (int k = 0; k < 128; k++) a2 += rs[k] * Wh[k * 128 + j];

    float hv = fmaxf(a2 + bh[j], 0.f);
    float contrib = hv * (which ? Wh2[j] : Wace[j]);
#pragma unroll
    for (int o = 16; o > 0; o >>= 1)
        contrib += __shfl_xor_sync(0xffffffffu, contrib, o);
    if ((j & 31) == 0) red[j >> 5] = contrib;
    __syncthreads();
    if (j == 0)
        out[bt] = red[0] + red[1] + red[2] + red[3] + (which ? bh2[0] : bace[0]);
}

// ---------------- host orchestration ----------------------------------------
extern "C" void kernel_launch(void* const* d_in, const int* in_sizes, int n_in,
                              void* d_out, int out_size) {
    const float* x    = (const float*)d_in[0];
    const int*   ei   = (const int*)  d_in[1];
    const float* ew   = (const float*)d_in[2];
    const int*   ace  = (const int*)  d_in[3];
    const int*   h2i  = (const int*)  d_in[4];
    const float* W1   = (const float*)d_in[5];
    const float* b1   = (const float*)d_in[6];
    const float* W2   = (const float*)d_in[7];
    const float* b2   = (const float*)d_in[8];
    const float* W3   = (const float*)d_in[9];
    const float* b3   = (const float*)d_in[10];
    const float* Wh   = (const float*)d_in[11];
    const float* bh   = (const float*)d_in[12];
    const float* Wace = (const float*)d_in[13];
    const float* bace = (const float*)d_in[14];
    const float* Wh2  = (const float*)d_in[15];
    const float* bh2  = (const float*)d_in[16];
    float* out = (float*)d_out;

    const int* src = ei;
    const int* dst = ei + N_EDGES;

    __half *xwA, *xwB;
    uint4 *apk, *w2pk, *w3pk;
    cudaGetSymbolAddress((void**)&xwA,  g_xwA);
    cudaGetSymbolAddress((void**)&xwB,  g_xwB);
    cudaGetSymbolAddress((void**)&apk,  g_apk);
    cudaGetSymbolAddress((void**)&w2pk, g_w2pk);
    cudaGetSymbolAddress((void**)&w3pk, g_w3pk);

    static cudaStream_t s1 = nullptr;
    static cudaEvent_t evFork = nullptr, evJoin = nullptr;
    if (!s1) {
        cudaStreamCreateWithFlags(&s1, cudaStreamNonBlocking);
        cudaEventCreateWithFlags(&evFork, cudaEventDisableTiming);
        cudaEventCreateWithFlags(&evJoin, cudaEventDisableTiming);
    }

    const int TPB = 256;
    int gGEMM = (N_NODES + 63) / 64;
    int gGATH = (N_NODES * 32 + TPB - 1) / TPB;

    // fork: layer-1 GEMM (independent of CSR) runs parallel to fused build
    cudaEventRecord(evFork, 0);
    cudaStreamWaitEvent(s1, evFork, 0);
    k_gemm1<<<gGEMM, 256, 0, s1>>>(x, W1, xwA, N_NODES);
    cudaEventRecord(evJoin, s1);

    // single fused build kernel (init+splitW / deg / scan / bucket), 1 blk/SM
    k_build<<<NBLD, 256>>>(W2, W3, src, dst, ew);

    // join: gather-1 needs both the CSR and xwA
    cudaStreamWaitEvent(0, evJoin, 0);
    k_gather_ps<<<gGATH, TPB>>>(xwA, b1, apk);

    // layer 2
    k_gemm_ps<<<gGEMM, 256>>>(apk, w2pk, xwB, N_NODES);
    k_gather_ps<<<gGATH, TPB>>>(xwB, b2, apk);

    // layer 3 (no full gather; head gathers per target)
    k_gemm_ps<<<gGEMM, 256>>>(apk, w3pk, xwA, N_NODES);

    // head
    k_head<<<2 * T_TGT, 128>>>(xwA, b3, ace, h2i, Wh, bh, Wace, bace, Wh2, bh2, out);
}

// round 17
// speedup vs baseline: 1.9438x; 1.9438x over previous
#include <cuda_runtime.h>
#include <cuda_bf16.h>
#include <cuda_fp16.h>
#include <cstdint>

#define N_NODES 50000
#define N_EDGES 640000
#define HD      128
#define T_TGT   100
#define NB_SCAN ((N_NODES + 255) / 256)    // 196
#define SEL_CAP 16384                       // cap on |S1| (expected ~2.8k)

// ---------------- scratch (static device globals) ---------------------------
__device__ float g_deg   [N_NODES];
__device__ int   g_cnt   [N_NODES];
__device__ int   g_rowptr[N_NODES + 1];
__device__ int   g_pos   [N_EDGES];
__device__ int2  g_ecsr  [N_EDGES];
__device__ int   g_bsum  [NB_SCAN];
__device__ int   g_mark  [N_NODES];
__device__ int   g_nlist [SEL_CAP];
__device__ int   g_ncnt;
__device__ __align__(16) __half g_xwA[N_NODES * HD];
__device__ __align__(16) __half g_xwB[N_NODES * HD];
// interleaved bf16 planes: per 4-col group one uint4 {hi01, hi23, lo01, lo23}
__device__ __align__(16) uint4 g_apk [N_NODES * 32];
__device__ __align__(16) uint4 g_w2pk[HD * 32];
__device__ __align__(16) uint4 g_w3pk[HD * 32];

// ---------------- bf16 split helper ------------------------------------------
__device__ __forceinline__ void split2(float a, float b, uint32_t& hi, uint32_t& lo) {
    __nv_bfloat16 ha = __float2bfloat16_rn(a);
    __nv_bfloat16 hb = __float2bfloat16_rn(b);
    float ra = a - __bfloat162float(ha);
    float rb = b - __bfloat162float(hb);
    __nv_bfloat162 H; H.x = ha; H.y = hb;
    __nv_bfloat162 L; L.x = __float2bfloat16_rn(ra); L.y = __float2bfloat16_rn(rb);
    hi = *(uint32_t*)&H;
    lo = *(uint32_t*)&L;
}

// ---------------- fused prep: init + pre-split W2/W3 -------------------------
__global__ __launch_bounds__(256) void k_prep(const float* __restrict__ W2,
                                              const float* __restrict__ W3) {
    int i = blockIdx.x * blockDim.x + threadIdx.x;
    if (i < N_NODES) { g_deg[i] = 1.0f; g_cnt[i] = 0; g_mark[i] = 0; }
    if (i == 0) g_ncnt = 0;
    if (i < HD * HD / 4) {
        float4 v = ((const float4*)W2)[i];
        uint32_t h0, l0, h1, l1;
        split2(v.x, v.y, h0, l0);
        split2(v.z, v.w, h1, l1);
        g_w2pk[i] = make_uint4(h0, h1, l0, l1);
        v = ((const float4*)W3)[i];
        split2(v.x, v.y, h0, l0);
        split2(v.z, v.w, h1, l1);
        g_w3pk[i] = make_uint4(h0, h1, l0, l1);
    }
}

__global__ void k_deg_count(const int* __restrict__ dst, const float* __restrict__ ew) {
    int e = blockIdx.x * blockDim.x + threadIdx.x;
    if (e < N_EDGES) {
        int d = dst[e];
        g_pos[e] = atomicAdd(&g_cnt[d], 1);
        atomicAdd(&g_deg[d], ew[e]);
    }
}

__global__ __launch_bounds__(256) void k_scan1() {
    __shared__ int sh[256];
    int t = threadIdx.x;
    int i = blockIdx.x * 256 + t;
    sh[t] = (i < N_NODES) ? g_cnt[i] : 0;
    __syncthreads();
    for (int off = 128; off > 0; off >>= 1) {
        if (t < off) sh[t] += sh[t + off];
        __syncthreads();
    }
    if (t == 0) g_bsum[blockIdx.x] = sh[0];
}

__global__ __launch_bounds__(256) void k_scan23() {
    __shared__ int bs[256];
    __shared__ int sh[256];
    int t = threadIdx.x;
    bs[t] = (t < NB_SCAN) ? g_bsum[t] : 0;
    __syncthreads();
    for (int off = 1; off < 256; off <<= 1) {
        int x = (t >= off) ? bs[t - off] : 0;
        __syncthreads();
        bs[t] += x;
        __syncthreads();
    }
    int blockOff = (blockIdx.x == 0) ? 0 : bs[blockIdx.x - 1];

    int i = blockIdx.x * 256 + t;
    int v = (i < N_NODES) ? g_cnt[i] : 0;
    sh[t] = v;
    __syncthreads();
    for (int off = 1; off < 256; off <<= 1) {
        int x = (t >= off) ? sh[t - off] : 0;
        __syncthreads();
        sh[t] += x;
        __syncthreads();
    }
    if (i < N_NODES) {
        g_rowptr[i] = blockOff + sh[t] - v;
        float d = g_deg[i];
        g_deg[i] = rsqrtf(fmaxf(d, 1e-12f));
    }
    if (i == 0) g_rowptr[N_NODES] = N_EDGES;
}

__global__ void k_bucket(const int* __restrict__ src, const int* __restrict__ dst,
                         const float* __restrict__ ew) {
    int e = blockIdx.x * blockDim.x + threadIdx.x;
    if (e < N_EDGES) {
        int d = dst[e];
        int s = src[e];
        float c = g_deg[s] * ew[e] * g_deg[d];
        g_ecsr[g_rowptr[d] + g_pos[e]] = make_int2(s, __float_as_int(c));
    }
}

// ---------------- mark S1 = targets U in-neighbors(targets) ------------------
__device__ __forceinline__ void try_add(int n) {
    if (atomicExch(&g_mark[n], 1) == 0) {
        int p = atomicAdd(&g_ncnt, 1);
        if (p < SEL_CAP) g_nlist[p] = n;
    }
}

__global__ __launch_bounds__(256) void k_mark(const int* __restrict__ ace_idx,
                                              const int* __restrict__ h2_idx) {
    int w    = (blockIdx.x * blockDim.x + threadIdx.x) >> 5;
    int lane = threadIdx.x & 31;
    if (w >= 2 * T_TGT) return;
    int node = (w < T_TGT) ? ace_idx[w] : h2_idx[w - T_TGT];
    if (lane == 0) try_add(node);
    int beg = g_rowptr[node];
    int end = g_rowptr[node + 1];
    for (int i = beg + lane; i < end; i += 32) try_add(g_ecsr[i].x);
}

// ---------------- mma helpers ------------------------------------------------
__device__ __forceinline__ void ldm_x4(uint32_t r[4], uint32_t addr) {
    asm volatile("ldmatrix.sync.aligned.m8n8.x4.shared.b16 {%0,%1,%2,%3}, [%4];"
                 : "=r"(r[0]), "=r"(r[1]), "=r"(r[2]), "=r"(r[3]) : "r"(addr));
}
__device__ __forceinline__ void ldm_x2t(uint32_t r[2], uint32_t addr) {
    asm volatile("ldmatrix.sync.aligned.m8n8.x2.trans.shared.b16 {%0,%1}, [%2];"
                 : "=r"(r[0]), "=r"(r[1]) : "r"(addr));
}
__device__ __forceinline__ void mma_bf16(float c[4], const uint32_t a[4], const uint32_t b[2]) {
    asm volatile("mma.sync.aligned.m16n8k16.row.col.f32.bf16.bf16.f32 "
                 "{%0,%1,%2,%3}, {%4,%5,%6,%7}, {%8,%9}, {%0,%1,%2,%3};"
                 : "+f"(c[0]), "+f"(c[1]), "+f"(c[2]), "+f"(c[3])
                 : "r"(a[0]), "r"(a[1]), "r"(a[2]), "r"(a[3]), "r"(b[0]), "r"(b[1]));
}

// ---------------- layer-1 GEMM: xw(fp16) = x(fp32) @ W (on-the-fly split) ---
__global__ __launch_bounds__(256, 2) void k_gemm1(const float* __restrict__ A,
                                                  const float* __restrict__ W,
                                                  __half* __restrict__ Cxw, int M) {
    __shared__ uint32_t As_hi[64][20], As_lo[64][20];
    __shared__ uint32_t Bs_hi[32][68], Bs_lo[32][68];

    const int tid  = threadIdx.x;
    const int lane = tid & 31;
    const int wid  = tid >> 5;
    const int g    = lane >> 2;
    const int tig  = lane & 3;
    const int wm   = wid >> 2;
    const int wn   = wid & 3;
    const int row0 = blockIdx.x * 64;

    const uint32_t aH = (uint32_t)__cvta_generic_to_shared(&As_hi[0][0]);
    const uint32_t aL = (uint32_t)__cvta_generic_to_shared(&As_lo[0][0]);
    const uint32_t bH = (uint32_t)__cvta_generic_to_shared(&Bs_hi[0][0]);
    const uint32_t bL = (uint32_t)__cvta_generic_to_shared(&Bs_lo[0][0]);

    float acc[2][4][4];
#pragma unroll
    for (int mt = 0; mt < 2; mt++)
#pragma unroll
        for (int nt = 0; nt < 4; nt++)
#pragma unroll
            for (int i = 0; i < 4; i++) acc[mt][nt][i] = 0.0f;

    for (int k0 = 0; k0 < 128; k0 += 32) {
#pragma unroll
        for (int it = 0; it < 2; it++) {
            int idx = tid + it * 256;
            int r   = idx >> 3;
            int c4  = (idx & 7) * 4;
            float4 v = make_float4(0.f, 0.f, 0.f, 0.f);
            int gr = row0 + r;
            if (gr < M) v = *(const float4*)(A + (long)gr * 128 + k0 + c4);
            uint32_t h0, l0, h1, l1;
            split2(v.x, v.y, h0, l0);
            split2(v.z, v.w, h1, l1);
            int cw = c4 >> 1;
            As_hi[r][cw] = h0; As_hi[r][cw + 1] = h1;
            As_lo[r][cw] = l0; As_lo[r][cw + 1] = l1;
        }
#pragma unroll
        for (int it = 0; it < 4; it++) {
            int idx = tid + it * 256;
            int kr  = idx >> 5;
            int c4  = (idx & 31) * 4;
            float4 v = *(const float4*)(W + (long)(k0 + kr) * 128 + c4);
            uint32_t h0, l0, h1, l1;
            split2(v.x, v.y, h0, l0);
            split2(v.z, v.w, h1, l1);
            int cw = c4 >> 1;
            Bs_hi[kr][cw] = h0; Bs_hi[kr][cw + 1] = h1;
            Bs_lo[kr][cw] = l0; Bs_lo[kr][cw + 1] = l1;
        }
        __syncthreads();

#pragma unroll
        for (int kk = 0; kk < 32; kk += 16) {
            uint32_t Ah[2][4], Al[2][4];
#pragma unroll
            for (int mt = 0; mt < 2; mt++) {
                uint32_t off = (uint32_t)(wm * 32 + mt * 16 + (lane & 15)) * 80u
                             + (uint32_t)(kk + ((lane >> 4) << 3)) * 2u;
                ldm_x4(Ah[mt], aH + off);
                ldm_x4(Al[mt], aL + off);
            }
#pragma unroll
            for (int nt = 0; nt < 4; nt++) {
                uint32_t Bh[2], Bl[2];
                uint32_t off = (uint32_t)(kk + (lane & 15)) * 272u
                             + (uint32_t)(wn * 32 + nt * 8) * 2u;
                ldm_x2t(Bh, bH + off);
                ldm_x2t(Bl, bL + off);
#pragma unroll
                for (int mt = 0; mt < 2; mt++) {
                    mma_bf16(acc[mt][nt], Ah[mt], Bh);
                    mma_bf16(acc[mt][nt], Ah[mt], Bl);
                    mma_bf16(acc[mt][nt], Al[mt], Bh);
                }
            }
        }
        __syncthreads();
    }

    __half2* xh2 = (__half2*)Cxw;
#pragma unroll
    for (int mt = 0; mt < 2; mt++) {
        int r0 = row0 + wm * 32 + mt * 16 + g;
        int r1 = r0 + 8;
#pragma unroll
        for (int nt = 0; nt < 4; nt++) {
            int colh = (wn * 32 + nt * 8 + 2 * tig) >> 1;
            if (r0 < M)
                xh2[(long)r0 * 64 + colh] = __floats2half2_rn(acc[mt][nt][0], acc[mt][nt][1]);
            if (r1 < M)
                xh2[(long)r1 * 64 + colh] = __floats2half2_rn(acc[mt][nt][2], acc[mt][nt][3]);
        }
    }
}

// ---------------- pre-split GEMM (full or selected rows via nlist) -----------
// SEL=false: rows are 0..M-1.  SEL=true: row r -> node g_nlist[r], r < g_ncnt.
template <bool SEL>
__global__ __launch_bounds__(256, 2) void k_gemm_ps(const uint4* __restrict__ apk,
                                                    const uint4* __restrict__ wpk,
                                                    __half* __restrict__ Cxw, int M) {
    __shared__ uint32_t As_hi[64][20], As_lo[64][20];
    __shared__ uint32_t Bs_hi[32][68], Bs_lo[32][68];

    const int tid  = threadIdx.x;
    const int lane = tid & 31;
    const int wid  = tid >> 5;
    const int g    = lane >> 2;
    const int tig  = lane & 3;
    const int wm   = wid >> 2;
    const int wn   = wid & 3;
    const int row0 = blockIdx.x * 64;

    int nrows = SEL ? g_ncnt : M;
    if (row0 >= nrows) return;              // whole block out of range (uniform)

    const uint32_t aH = (uint32_t)__cvta_generic_to_shared(&As_hi[0][0]);
    const uint32_t aL = (uint32_t)__cvta_generic_to_shared(&As_lo[0][0]);
    const uint32_t bH = (uint32_t)__cvta_generic_to_shared(&Bs_hi[0][0]);
    const uint32_t bL = (uint32_t)__cvta_generic_to_shared(&Bs_lo[0][0]);

    float acc[2][4][4];
#pragma unroll
    for (int mt = 0; mt < 2; mt++)
#pragma unroll
        for (int nt = 0; nt < 4; nt++)
#pragma unroll
            for (int i = 0; i < 4; i++) acc[mt][nt][i] = 0.0f;

    for (int k0 = 0; k0 < 128; k0 += 32) {
#pragma unroll
        for (int it = 0; it < 2; it++) {
            int idx = tid + it * 256;
            int r   = idx >> 3;
            int wg  = idx & 7;
            int gr  = row0 + r;
            uint4 u = make_uint4(0u, 0u, 0u, 0u);
            if (gr < nrows) {
                long node = SEL ? (long)g_nlist[gr] : (long)gr;
                u = apk[node * 32 + (k0 >> 2) + wg];
            }
            As_hi[r][wg * 2] = u.x; As_hi[r][wg * 2 + 1] = u.y;
            As_lo[r][wg * 2] = u.z; As_lo[r][wg * 2 + 1] = u.w;
        }
#pragma unroll
        for (int it = 0; it < 4; it++) {
            int idx = tid + it * 256;
            int kr  = idx >> 5;
            int cg  = idx & 31;
            uint4 u = wpk[(long)(k0 + kr) * 32 + cg];
            Bs_hi[kr][cg * 2] = u.x; Bs_hi[kr][cg * 2 + 1] = u.y;
            Bs_lo[kr][cg * 2] = u.z; Bs_lo[kr][cg * 2 + 1] = u.w;
        }
        __syncthreads();

#pragma unroll
        for (int kk = 0; kk < 32; kk += 16) {
            uint32_t Ah[2][4], Al[2][4];
#pragma unroll
            for (int mt = 0; mt < 2; mt++) {
                uint32_t off = (uint32_t)(wm * 32 + mt * 16 + (lane & 15)) * 80u
                             + (uint32_t)(kk + ((lane >> 4) << 3)) * 2u;
                ldm_x4(Ah[mt], aH + off);
                ldm_x4(Al[mt], aL + off);
            }
#pragma unroll
            for (int nt = 0; nt < 4; nt++) {
                uint32_t Bh[2], Bl[2];
                uint32_t off = (uint32_t)(kk + (lane & 15)) * 272u
                             + (uint32_t)(wn * 32 + nt * 8) * 2u;
                ldm_x2t(Bh, bH + off);
                ldm_x2t(Bl, bL + off);
#pragma unroll
                for (int mt = 0; mt < 2; mt++) {
                    mma_bf16(acc[mt][nt], Ah[mt], Bh);
                    mma_bf16(acc[mt][nt], Ah[mt], Bl);
                    mma_bf16(acc[mt][nt], Al[mt], Bh);
                }
            }
        }
        __syncthreads();
    }

    __half2* xh2 = (__half2*)Cxw;
#pragma unroll
    for (int mt = 0; mt < 2; mt++) {
        int r0 = row0 + wm * 32 + mt * 16 + g;
        int r1 = r0 + 8;
        long n0 = (r0 < nrows) ? (SEL ? (long)g_nlist[r0] : (long)r0) : -1;
        long n1 = (r1 < nrows) ? (SEL ? (long)g_nlist[r1] : (long)r1) : -1;
#pragma unroll
        for (int nt = 0; nt < 4; nt++) {
            int colh = (wn * 32 + nt * 8 + 2 * tig) >> 1;
            if (n0 >= 0)
                xh2[n0 * 64 + colh] = __floats2half2_rn(acc[mt][nt][0], acc[mt][nt][1]);
            if (n1 >= 0)
                xh2[n1 * 64 + colh] = __floats2half2_rn(acc[mt][nt][2], acc[mt][nt][3]);
        }
    }
}

// ---------------- CSR gather + bias + relu -> interleaved bf16 planes --------
// SEL=false: warp w -> node w. SEL=true: warp w -> g_nlist[w], w < g_ncnt.
template <bool SEL>
__global__ __launch_bounds__(256) void k_gather_ps(const __half* __restrict__ xw,
                                                   const float* __restrict__ bias,
                                                   uint4* __restrict__ apk) {
    int w    = (blockIdx.x * blockDim.x + threadIdx.x) >> 5;
    int lane = threadIdx.x & 31;
    int nrows = SEL ? g_ncnt : N_NODES;
    if (w >= nrows) return;
    int node = SEL ? g_nlist[w] : w;

    int beg = g_rowptr[node];
    int end = g_rowptr[node + 1];
    float di = g_deg[node];
    float s  = di * di;

    const uint2* xv = (const uint2*)xw;

    float4 acc;
    {
        uint2 u = __ldg(&xv[(long)node * 32 + lane]);
        float2 a = __half22float2(*(__half2*)&u.x);
        float2 b = __half22float2(*(__half2*)&u.y);
        acc = make_float4(s * a.x, s * a.y, s * b.x, s * b.y);
    }

    int i = beg;
    for (; i + 8 <= end; i += 8) {
        int2  p[8];
        uint2 u[8];
#pragma unroll
        for (int j = 0; j < 8; j++) p[j] = __ldg(&g_ecsr[i + j]);
#pragma unroll
        for (int j = 0; j < 8; j++) u[j] = __ldg(&xv[(long)p[j].x * 32 + lane]);
#pragma unroll
        for (int j = 0; j < 8; j++) {
            float c = __int_as_float(p[j].y);
            float2 a = __half22float2(*(__half2*)&u[j].x);
            float2 b = __half22float2(*(__half2*)&u[j].y);
            acc.x += c * a.x; acc.y += c * a.y; acc.z += c * b.x; acc.w += c * b.y;
        }
    }
    for (; i + 2 <= end; i += 2) {
        int2 p0 = __ldg(&g_ecsr[i]);
        int2 p1 = __ldg(&g_ecsr[i + 1]);
        uint2 u0 = __ldg(&xv[(long)p0.x * 32 + lane]);
        uint2 u1 = __ldg(&xv[(long)p1.x * 32 + lane]);
        float c0 = __int_as_float(p0.y), c1 = __int_as_float(p1.y);
        float2 a, b;
        a = __half22float2(*(__half2*)&u0.x); b = __half22float2(*(__half2*)&u0.y);
        acc.x += c0 * a.x; acc.y += c0 * a.y; acc.z += c0 * b.x; acc.w += c0 * b.y;
        a = __half22float2(*(__half2*)&u1.x); b = __half22float2(*(__half2*)&u1.y);
        acc.x += c1 * a.x; acc.y += c1 * a.y; acc.z += c1 * b.x; acc.w += c1 * b.y;
    }
    if (i < end) {
        int2 p = __ldg(&g_ecsr[i]);
        float c = __int_as_float(p.y);
        uint2 u = __ldg(&xv[(long)p.x * 32 + lane]);
        float2 a = __half22float2(*(__half2*)&u.x);
        float2 b = __half22float2(*(__half2*)&u.y);
        acc.x += c * a.x; acc.y += c * a.y; acc.z += c * b.x; acc.w += c * b.y;
    }

    float4 bb = *(const float4*)(bias + lane * 4);
    acc.x = fmaxf(acc.x + bb.x, 0.f);
    acc.y = fmaxf(acc.y + bb.y, 0.f);
    acc.z = fmaxf(acc.z + bb.z, 0.f);
    acc.w = fmaxf(acc.w + bb.w, 0.f);

    uint32_t h0, l0, h1, l1;
    split2(acc.x, acc.y, h0, l0);
    split2(acc.z, acc.w, h1, l1);
    apk[(long)node * 32 + lane] = make_uint4(h0, h1, l0, l1);
}

// ---------------- head: per-target CSR gather + MLP --------------------------
__global__ __launch_bounds__(128) void k_head(const __half* __restrict__ xw3,
                                              const float* __restrict__ b3,
                                              const int* __restrict__ ace_idx,
                                              const int* __restrict__ h2_idx,
                                              const float* __restrict__ Wh,
                                              const float* __restrict__ bh,
                                              const float* __restrict__ Wace,
                                              const float* __restrict__ bace,
                                              const float* __restrict__ Wh2,
                                              const float* __restrict__ bh2,
                                              float* __restrict__ out) {
    __shared__ float rs[128];
    __shared__ float red[4];
    int bt    = blockIdx.x;
    int which = bt / T_TGT;
    int t     = bt - which * T_TGT;
    int node  = which ? h2_idx[t] : ace_idx[t];
    int j     = threadIdx.x;

    float di  = g_deg[node];
    float acc = di * di * __half2float(xw3[(long)node * 128 + j]);
    int beg = g_rowptr[node];
    int end = g_rowptr[node + 1];
    for (int i = beg; i < end; i++) {
        int2 p = g_ecsr[i];
        acc += __int_as_float(p.y) * __half2float(xw3[(long)p.x * 128 + j]);
    }
    rs[j] = fmaxf(acc + b3[j], 0.f);
    __syncthreads();

    float a2 = 0.f;
#pragma unroll 8
    for (int k = 0; k < 128; k++) a2 += rs[k] * Wh[k * 128 + j];

    float hv = fmaxf(a2 + bh[j], 0.f);
    float contrib = hv * (which ? Wh2[j] : Wace[j]);
#pragma unroll
    for (int o = 16; o > 0; o >>= 1)
        contrib += __shfl_xor_sync(0xffffffffu, contrib, o);
    if ((j & 31) == 0) red[j >> 5] = contrib;
    __syncthreads();
    if (j == 0)
        out[bt] = red[0] + red[1] + red[2] + red[3] + (which ? bh2[0] : bace[0]);
}

// ---------------- host orchestration ----------------------------------------
extern "C" void kernel_launch(void* const* d_in, const int* in_sizes, int n_in,
                              void* d_out, int out_size) {
    const float* x    = (const float*)d_in[0];
    const int*   ei   = (const int*)  d_in[1];
    const float* ew   = (const float*)d_in[2];
    const int*   ace  = (const int*)  d_in[3];
    const int*   h2i  = (const int*)  d_in[4];
    const float* W1   = (const float*)d_in[5];
    const float* b1   = (const float*)d_in[6];
    const float* W2   = (const float*)d_in[7];
    const float* b2   = (const float*)d_in[8];
    const float* W3   = (const float*)d_in[9];
    const float* b3   = (const float*)d_in[10];
    const float* Wh   = (const float*)d_in[11];
    const float* bh   = (const float*)d_in[12];
    const float* Wace = (const float*)d_in[13];
    const float* bace = (const float*)d_in[14];
    const float* Wh2  = (const float*)d_in[15];
    const float* bh2  = (const float*)d_in[16];
    float* out = (float*)d_out;

    const int* src = ei;
    const int* dst = ei + N_EDGES;

    __half *xwA, *xwB;
    uint4 *apk, *w2pk, *w3pk;
    cudaGetSymbolAddress((void**)&xwA,  g_xwA);
    cudaGetSymbolAddress((void**)&xwB,  g_xwB);
    cudaGetSymbolAddress((void**)&apk,  g_apk);
    cudaGetSymbolAddress((void**)&w2pk, g_w2pk);
    cudaGetSymbolAddress((void**)&w3pk, g_w3pk);

    static cudaStream_t s1 = nullptr;
    static cudaEvent_t evFork = nullptr, evJoin = nullptr;
    if (!s1) {
        cudaStreamCreateWithFlags(&s1, cudaStreamNonBlocking);
        cudaEventCreateWithFlags(&evFork, cudaEventDisableTiming);
        cudaEventCreateWithFlags(&evJoin, cudaEventDisableTiming);
    }

    const int TPB = 256;
    int gE    = (N_EDGES + TPB - 1) / TPB;
    int gGEMM = (N_NODES + 63) / 64;
    int gGATH = (N_NODES * 32 + TPB - 1) / TPB;
    int gGATS = (SEL_CAP * 32 + TPB - 1) / TPB;     // selected gather (cap)
    int gGEMS = (SEL_CAP + 63) / 64;                // selected gemm (cap)
    int gMARK = (2 * T_TGT * 32 + TPB - 1) / TPB;

    // fork: layer-1 GEMM runs parallel to CSR build
    cudaEventRecord(evFork, 0);
    cudaStreamWaitEvent(s1, evFork, 0);
    k_gemm1<<<gGEMM, 256, 0, s1>>>(x, W1, xwA, N_NODES);
    cudaEventRecord(evJoin, s1);

    // CSR + dinv build + weight pre-split + S1 marking (legacy stream)
    k_prep<<<NB_SCAN, 256>>>(W2, W3);
    k_deg_count<<<gE, TPB>>>(dst, ew);
    k_scan1<<<NB_SCAN, 256>>>();
    k_scan23<<<NB_SCAN, 256>>>();
    k_bucket<<<gE, TPB>>>(src, dst, ew);
    k_mark<<<gMARK, TPB>>>(ace, h2i);

    // join: gather-1 needs both the CSR and xwA
    cudaStreamWaitEvent(0, evJoin, 0);
    k_gather_ps<false><<<gGATH, TPB>>>(xwA, b1, apk);

    // layer 2 (full)
    k_gemm_ps<false><<<gGEMM, 256>>>(apk, w2pk, xwB, N_NODES);

    // layer 3: only S1 rows needed (head reads agg3 of targets only)
    k_gather_ps<true><<<gGATS, TPB>>>(xwB, b2, apk);
    k_gemm_ps<true><<<gGEMS, 256>>>(apk, w3pk, xwA, 0);

    // head
    k_head<<<2 * T_TGT, 128>>>(xwA, b3, ace, h2i, Wh, bh, Wace, bace, Wh2, bh2, out);
}